// round 7
// baseline (speedup 1.0000x reference)
#include <cuda_runtime.h>
#include <cuda_fp16.h>
#include <cstdint>

// ============================ problem constants ============================
#define IN_DIM   4096
#define OUT_DIM  11008
#define BATCH    64
#define GROUP    128
#define BK       128                 // K per mainloop iteration == GROUP
#define KSPLIT   4
#define NKB_TOT  (IN_DIM / BK)       // 32 k-blocks total
#define NKB_CTA  (NKB_TOT / KSPLIT)  // 8 k-blocks per CTA
#define CTA_N    128                 // output channels per CTA
#define NTILES   (OUT_DIM / CTA_N)   // 86
#define NCTA     (NTILES * KSPLIT)   // 344
#define NTHREADS 256                 // 8 warps: 2 (M) x 4 (N)

// ---- SMEM stage layout (bytes, relative to stage base) ----
#define A_BYTES   16384              // x tile: 64 rows x 256B
#define W_BYTES   8192               // qweight tile: 16 rows x 512B
#define S_OFF     (A_BYTES + W_BYTES)          // 24576
#define Z_OFF     (S_OFF + 512)                 // 25088
#define STAGE     25600
#define NSTAGE    3
#define W16_OFF   (NSTAGE * STAGE)              // 76800: dequantized W fp16 [128ch x 256B]
#define W16_BYTES 32768
#define SMEM_ALLOC (W16_OFF + W16_BYTES + 1024) // 110592; x2 CTAs = 221184 <= 228KB/SM

// x pre-converted to fp16 with intra-8 k-permutation [0,4,1,5,2,6,3,7]
__device__ __align__(16) __half g_xperm[BATCH * IN_DIM];

// ============================ helpers ============================
__device__ __forceinline__ uint32_t smem_u32(const void* p) {
    uint32_t a;
    asm("{ .reg .u64 t; cvta.to.shared.u64 t, %1; cvt.u32.u64 %0, t; }" : "=r"(a) : "l"(p));
    return a;
}

// magic dequant: nibbles (j, j+4) of q (j = sh/4) -> fp16x2 (v - z) * s.
__device__ __forceinline__ uint32_t dq_pair(uint32_t q, int sh, __half2 s2, __half2 b2) {
    uint32_t p = ((q >> sh) & 0x000F000Fu) | 0x64006400u;
    __half2 hv = *reinterpret_cast<__half2*>(&p);
    const __half2 c1024 = __half2half2(__ushort_as_half((unsigned short)0x6400u));
    __half2 w = __hfma2(__hsub2(hv, c1024), s2, b2);   // (v - z) * s
    return *reinterpret_cast<uint32_t*>(&w);
}

__device__ __forceinline__ void mma16816(float* c, const uint32_t* a, uint32_t b0, uint32_t b1) {
    asm volatile(
        "mma.sync.aligned.m16n8k16.row.col.f32.f16.f16.f32 "
        "{%0,%1,%2,%3}, {%4,%5,%6,%7}, {%8,%9}, {%0,%1,%2,%3};"
        : "+f"(c[0]), "+f"(c[1]), "+f"(c[2]), "+f"(c[3])
        : "r"(a[0]), "r"(a[1]), "r"(a[2]), "r"(a[3]), "r"(b0), "r"(b1));
}

__device__ __forceinline__ void ldmatrix_x4(uint32_t* r, uint32_t addr) {
    asm volatile("ldmatrix.sync.aligned.m8n8.x4.shared.b16 {%0,%1,%2,%3}, [%4];"
                 : "=r"(r[0]), "=r"(r[1]), "=r"(r[2]), "=r"(r[3]) : "r"(addr));
}

__device__ __forceinline__ void sts128(uint32_t addr, uint4 v) {
    asm volatile("st.shared.v4.b32 [%0], {%1,%2,%3,%4};"
                 :: "r"(addr), "r"(v.x), "r"(v.y), "r"(v.z), "r"(v.w) : "memory");
}

__device__ __forceinline__ void cp_async16(uint32_t dst, const void* src) {
    asm volatile("cp.async.cg.shared.global [%0], [%1], 16;" :: "r"(dst), "l"(src));
}
#define CP_COMMIT() asm volatile("cp.async.commit_group;" ::: "memory")
#define CP_WAIT(n)  asm volatile("cp.async.wait_group %0;" :: "n"(n) : "memory")

// fire-and-forget global float add (REDG)
__device__ __forceinline__ void redg_add(float* p, float v) {
    asm volatile("red.global.add.f32 [%0], %1;" :: "l"(p), "f"(v) : "memory");
}

// ============================ x pre-permute kernel ============================
__global__ void __launch_bounds__(256) xperm_kernel(const float* __restrict__ x) {
    int idx = blockIdx.x * blockDim.x + threadIdx.x;   // one 8-float chunk
    if (idx >= BATCH * IN_DIM / 8) return;
    const float4* p = reinterpret_cast<const float4*>(x) + (size_t)idx * 2;
    float4 a = p[0], b = p[1];
    __half2 h0 = __floats2half2_rn(a.x, b.x);
    __half2 h1 = __floats2half2_rn(a.y, b.y);
    __half2 h2 = __floats2half2_rn(a.z, b.z);
    __half2 h3 = __floats2half2_rn(a.w, b.w);
    uint4 o;
    o.x = *reinterpret_cast<uint32_t*>(&h0);
    o.y = *reinterpret_cast<uint32_t*>(&h1);
    o.z = *reinterpret_cast<uint32_t*>(&h2);
    o.w = *reinterpret_cast<uint32_t*>(&h3);
    reinterpret_cast<uint4*>(g_xperm)[idx] = o;
}

// ============================ main kernel ============================
// Grid: 344 CTAs = 86 n-tiles x 4 k-splits.
// Warp grid 2(M) x 4(N): warp (mw,nw) computes batch rows [32mw,32mw+32) x
// channels [32nw, 32nw+32). Per k-block: cooperative dequant of W into SMEM fp16,
// then a pure LDSM+HMMA inner loop. Epilogue: red.global.add into out.
__global__ void __launch_bounds__(NTHREADS, 2)
mpq_kernel(const uint32_t* __restrict__ qweight,
           const float* __restrict__ scales,
           const float* __restrict__ zeros,
           float* __restrict__ out) {
    extern __shared__ __align__(128) uint8_t smraw[];
    uint8_t* sm = (uint8_t*)(((uintptr_t)smraw + 1023u) & ~(uintptr_t)1023u);
    const uint32_t sbase = smem_u32(sm);

    const int t     = threadIdx.x;
    const int lane  = t & 31;
    const int wid   = t >> 5;
    const int mw    = wid >> 2;        // 0..1: batch-row group
    const int nw    = wid & 3;         // 0..3: channel group
    const int ntile = blockIdx.x % NTILES;
    const int split = blockIdx.x / NTILES;
    const int nbase = ntile * CTA_N;
    const int kb0   = split * NKB_CTA;

    // ---- stage loader (pure cp.async) ----
    auto load_stage = [&](int stage, int kbg) {
        uint32_t stb = sbase + stage * STAGE;
        // A: x tile, 64 rows x 256B, XOR-swizzled in 16B chunks
        {
            int row = t >> 2;
            int cg  = t & 3;
            const __half* src = g_xperm + (size_t)row * IN_DIM + kbg * BK;
            uint32_t dst_row = stb + row * 256;
            int rx = row & 7;
#pragma unroll
            for (int i = 0; i < 4; i++) {
                int c = cg * 4 + i;
                cp_async16(dst_row + (uint32_t)((c ^ rx) * 16), src + c * 8);
            }
        }
        // W: qweight rows kbg*16..+16, channels nbase..+128 (512B/row, linear)
        {
            const uint32_t* wsrc = qweight + (size_t)(kbg * 16) * OUT_DIM + nbase;
            uint32_t dstW = stb + A_BYTES;
#pragma unroll
            for (int i = 0; i < 2; i++) {
                int id = t * 2 + i;          // 0..511
                int r = id >> 5, c = id & 31;
                cp_async16(dstW + (uint32_t)id * 16, wsrc + (size_t)r * OUT_DIM + c * 4);
            }
        }
        // S/Z: 128 floats each
        if (t < 32) {
            cp_async16(stb + S_OFF + t * 16, scales + (size_t)kbg * OUT_DIM + nbase + t * 4);
        } else if (t < 64) {
            int u = t - 32;
            cp_async16(stb + Z_OFF + u * 16, zeros + (size_t)kbg * OUT_DIM + nbase + u * 4);
        }
    };

    float acc[4][2][4];                // [n-tile][m-tile][frag]
#pragma unroll
    for (int nt = 0; nt < 4; nt++)
#pragma unroll
        for (int mt = 0; mt < 2; mt++)
#pragma unroll
            for (int i = 0; i < 4; i++) acc[nt][mt][i] = 0.f;

    // A-ldmatrix lane addressing
    const int lm_m  = lane & 15;       // row within m16 tile
    const int lm_kh = lane >> 4;       // k-half (0/1)
    // B-ldmatrix lane addressing: quad q supplies matrix q's rows
    const int bq  = lane >> 3;         // 0..3
    const int br  = lane & 7;
    const int bko = bq & 1;            // k-half of matrix
    const int bc0 = nw * 32 + (bq >> 1) * 8 + br;   // channel row, bt adds +16
    const uint32_t wb = sbase + W16_OFF;

    // dequant ownership: thread t -> channel (t&127), kp-half (t>>7)
    const int dq_ch  = t & 127;
    const int dq_kp0 = (t >> 7) * 8;
    const int dq_cx  = dq_ch & 7;
    const uint32_t dq_wrow = wb + dq_ch * 256;

    load_stage(0, kb0 + 0); CP_COMMIT();
    load_stage(1, kb0 + 1); CP_COMMIT();

#pragma unroll 1
    for (int kb = 0; kb < NKB_CTA; kb++) {
        const int s = kb % NSTAGE;
        if (kb + 1 < NKB_CTA) { CP_WAIT(1); } else { CP_WAIT(0); }
        __syncthreads();   // all warps done reading stage (kb-1)%3 == (kb+2)%3
        if (kb + 2 < NKB_CTA) {
            load_stage((kb + 2) % NSTAGE, kb0 + kb + 2);
            CP_COMMIT();
        }

        const uint8_t* stb = sm + s * STAGE;
        const uint32_t ab  = sbase + s * STAGE;

        // ---- cooperative dequant: qweight int4 -> W16 fp16 [128ch x 256B] ----
        {
            const uint32_t* smWq = (const uint32_t*)(stb + A_BYTES);
            const float*    smS  = (const float*)(stb + S_OFF);
            const float*    smZ  = (const float*)(stb + Z_OFF);
            float sc = smS[dq_ch];
            float zr = smZ[dq_ch];
            __half2 s2 = __float2half2_rn(sc);
            __half2 b2 = __float2half2_rn(-zr * sc);
#pragma unroll
            for (int i = 0; i < 8; i++) {
                int kp = dq_kp0 + i;
                uint32_t q = smWq[kp * 128 + dq_ch];
                uint4 ws;
                ws.x = dq_pair(q, 0,  s2, b2);
                ws.y = dq_pair(q, 4,  s2, b2);
                ws.z = dq_pair(q, 8,  s2, b2);
                ws.w = dq_pair(q, 12, s2, b2);
                sts128(dq_wrow + (uint32_t)((kp ^ dq_cx) * 16), ws);
            }
        }
        __syncthreads();   // W16 visible to all warps

        // ---- pure LDSM + HMMA inner loop ----
#pragma unroll
        for (int s16 = 0; s16 < 8; s16++) {
            uint32_t a[2][4], b[2][4];
#pragma unroll
            for (int mt = 0; mt < 2; mt++) {
                int m = mw * 32 + mt * 16 + lm_m;
                uint32_t addr = ab + (uint32_t)(m * 256)
                              + (uint32_t)(((2 * s16 + lm_kh) ^ (m & 7)) * 16);
                ldmatrix_x4(a[mt], addr);
            }
#pragma unroll
            for (int bt = 0; bt < 2; bt++) {
                int ch = bc0 + bt * 16;
                uint32_t addr = wb + (uint32_t)(ch * 256)
                              + (uint32_t)(((2 * s16 + bko) ^ (ch & 7)) * 16);
                ldmatrix_x4(b[bt], addr);
            }
#pragma unroll
            for (int bt = 0; bt < 2; bt++)
#pragma unroll
                for (int h = 0; h < 2; h++) {
                    int nt = 2 * bt + h;
                    uint32_t b0 = b[bt][2 * h], b1 = b[bt][2 * h + 1];
#pragma unroll
                    for (int mt = 0; mt < 2; mt++)
                        mma16816(acc[nt][mt], a[mt], b0, b1);
                }
        }
        __syncthreads();   // all warps done with W16 before next kb overwrites it
    }

    // ---- epilogue: accumulate into out via fire-and-forget global adds ----
#pragma unroll
    for (int nt = 0; nt < 4; nt++) {
        int n = nbase + nw * 32 + nt * 8 + (lane & 3) * 2;
#pragma unroll
        for (int mt = 0; mt < 2; mt++) {
            int m = mw * 32 + mt * 16 + (lane >> 2);
            float* p0 = out + (size_t)m * OUT_DIM + n;
            float* p1 = out + (size_t)(m + 8) * OUT_DIM + n;
            redg_add(p0,     acc[nt][mt][0]);
            redg_add(p0 + 1, acc[nt][mt][1]);
            redg_add(p1,     acc[nt][mt][2]);
            redg_add(p1 + 1, acc[nt][mt][3]);
        }
    }
}

// ============================ launch ============================
extern "C" void kernel_launch(void* const* d_in, const int* in_sizes, int n_in,
                              void* d_out, int out_size) {
    (void)in_sizes; (void)n_in; (void)out_size;
    const float*    x       = (const float*)d_in[0];
    const uint32_t* qweight = (const uint32_t*)d_in[1];
    const float*    scales  = (const float*)d_in[2];
    const float*    zeros   = (const float*)d_in[3];
    // d_in[4] = g_idx (unused: g_idx[i] == i / GROUP by construction)
    float* out = (float*)d_out;

    cudaMemsetAsync(d_out, 0, (size_t)BATCH * OUT_DIM * sizeof(float));
    xperm_kernel<<<(BATCH * IN_DIM / 8 + 255) / 256, 256>>>(x);

    cudaFuncSetAttribute(mpq_kernel, cudaFuncAttributeMaxDynamicSharedMemorySize, SMEM_ALLOC);
    mpq_kernel<<<NCTA, NTHREADS, SMEM_ALLOC>>>(qweight, scales, zeros, out);
}

// round 8
// speedup vs baseline: 1.2466x; 1.2466x over previous
#include <cuda_runtime.h>
#include <cuda_fp16.h>
#include <cstdint>

// ============================ problem constants ============================
#define IN_DIM   4096
#define OUT_DIM  11008
#define BATCH    64
#define GROUP    128
#define BK       128                 // K per mainloop iteration == GROUP
#define KSPLIT   5                   // uneven splits {7,7,6,6,6}
#define NKB_TOT  (IN_DIM / BK)       // 32 k-blocks total
#define CTA_N    128                 // output channels per CTA
#define NTILES   (OUT_DIM / CTA_N)   // 86
#define NCTA     (NTILES * KSPLIT)   // 430
#define NTHREADS 256                 // 8 warps, each N=16 (full M=64)
#define WARP_N   16

// ---- SMEM stage layout (bytes, relative to stage base) ----
#define A_BYTES   16384              // x tile: 64 rows x 256B
#define W_BYTES   8192               // qweight tile: 16 rows x 512B
#define S_OFF     (A_BYTES + W_BYTES)          // 24576
#define Z_OFF     (S_OFF + 512)                 // 25088
#define STAGE     25600
#define NSTAGE    2
#define SMEM_ALLOC (NSTAGE * STAGE + 1024)      // 52224; x3 CTAs = 156672 <= 228KB

// x pre-converted to fp16 with intra-8 k-permutation [0,4,1,5,2,6,3,7]
__device__ __align__(16) __half g_xperm[BATCH * IN_DIM];

// ============================ helpers ============================
__device__ __forceinline__ uint32_t smem_u32(const void* p) {
    uint32_t a;
    asm("{ .reg .u64 t; cvta.to.shared.u64 t, %1; cvt.u32.u64 %0, t; }" : "=r"(a) : "l"(p));
    return a;
}

// magic dequant: nibbles (j, j+4) of q (j = sh/4) -> fp16x2 (v - z) * s.
__device__ __forceinline__ uint32_t dq_pair(uint32_t q, int sh, __half2 s2, __half2 b2) {
    uint32_t p = ((q >> sh) & 0x000F000Fu) | 0x64006400u;
    __half2 hv = *reinterpret_cast<__half2*>(&p);
    const __half2 c1024 = __half2half2(__ushort_as_half((unsigned short)0x6400u));
    __half2 w = __hfma2(__hsub2(hv, c1024), s2, b2);   // (v - z) * s
    return *reinterpret_cast<uint32_t*>(&w);
}

__device__ __forceinline__ void mma16816(float* c, const uint32_t* a, uint32_t b0, uint32_t b1) {
    asm volatile(
        "mma.sync.aligned.m16n8k16.row.col.f32.f16.f16.f32 "
        "{%0,%1,%2,%3}, {%4,%5,%6,%7}, {%8,%9}, {%0,%1,%2,%3};"
        : "+f"(c[0]), "+f"(c[1]), "+f"(c[2]), "+f"(c[3])
        : "r"(a[0]), "r"(a[1]), "r"(a[2]), "r"(a[3]), "r"(b0), "r"(b1));
}

__device__ __forceinline__ void ldmatrix_x4(uint32_t* r, uint32_t addr) {
    asm volatile("ldmatrix.sync.aligned.m8n8.x4.shared.b16 {%0,%1,%2,%3}, [%4];"
                 : "=r"(r[0]), "=r"(r[1]), "=r"(r[2]), "=r"(r[3]) : "r"(addr));
}

__device__ __forceinline__ void cp_async16(uint32_t dst, const void* src) {
    asm volatile("cp.async.cg.shared.global [%0], [%1], 16;" :: "r"(dst), "l"(src));
}
#define CP_COMMIT() asm volatile("cp.async.commit_group;" ::: "memory")
#define CP_WAIT(n)  asm volatile("cp.async.wait_group %0;" :: "n"(n) : "memory")

// fire-and-forget global float add (REDG)
__device__ __forceinline__ void redg_add(float* p, float v) {
    asm volatile("red.global.add.f32 [%0], %1;" :: "l"(p), "f"(v) : "memory");
}

// ============================ x pre-permute + out-zero kernel ============================
__global__ void __launch_bounds__(256) xperm_kernel(const float* __restrict__ x,
                                                    float* __restrict__ out) {
    int idx = blockIdx.x * blockDim.x + threadIdx.x;   // one 8-float chunk
    if (idx < BATCH * IN_DIM / 8) {
        const float4* p = reinterpret_cast<const float4*>(x) + (size_t)idx * 2;
        float4 a = p[0], b = p[1];
        __half2 h0 = __floats2half2_rn(a.x, b.x);
        __half2 h1 = __floats2half2_rn(a.y, b.y);
        __half2 h2 = __floats2half2_rn(a.z, b.z);
        __half2 h3 = __floats2half2_rn(a.w, b.w);
        uint4 o;
        o.x = *reinterpret_cast<uint32_t*>(&h0);
        o.y = *reinterpret_cast<uint32_t*>(&h1);
        o.z = *reinterpret_cast<uint32_t*>(&h2);
        o.w = *reinterpret_cast<uint32_t*>(&h3);
        reinterpret_cast<uint4*>(g_xperm)[idx] = o;
    }
    // zero d_out (REDG accumulates into it): 176128 float4s, grid-stride
    const float4 z = make_float4(0.f, 0.f, 0.f, 0.f);
    const int Q = BATCH * OUT_DIM / 4;
    for (int i = idx; i < Q; i += gridDim.x * blockDim.x)
        reinterpret_cast<float4*>(out)[i] = z;
}

// ============================ main kernel ============================
// Grid: 430 CTAs = 86 n-tiles x 5 k-splits (uneven {7,7,6,6,6} k-blocks).
// 8 warps each own N=16 channels, full M=64. 2-stage cp.async pipeline,
// one barrier per iteration, register-direct dequant, REDG epilogue.
__global__ void __launch_bounds__(NTHREADS, 3)
mpq_kernel(const uint32_t* __restrict__ qweight,
           const float* __restrict__ scales,
           const float* __restrict__ zeros,
           float* __restrict__ out) {
    extern __shared__ __align__(128) uint8_t smraw[];
    uint8_t* sm = (uint8_t*)(((uintptr_t)smraw + 1023u) & ~(uintptr_t)1023u);
    const uint32_t sbase = smem_u32(sm);

    const int t     = threadIdx.x;
    const int lane  = t & 31;
    const int wid   = t >> 5;
    const int kc    = lane & 3;        // k-pair selector within k16
    const int nl    = lane >> 2;       // n within 8-wide n-tile
    const int ntile = blockIdx.x % NTILES;
    const int split = blockIdx.x / NTILES;
    const int nbase = ntile * CTA_N;
    const int kb0   = split * 6 + (split < 2 ? split : 2);  // {0,7,14,20,26}
    const int nkb   = 6 + (split < 2 ? 1 : 0);              // {7,7,6,6,6}

    // ---- stage loader (pure cp.async) ----
    auto load_stage = [&](int stage, int kbg) {
        uint32_t stb = sbase + stage * STAGE;
        // A: x tile, 64 rows x 256B, XOR-swizzled in 16B chunks
        {
            int row = t >> 2;
            int cg  = t & 3;
            const __half* src = g_xperm + (size_t)row * IN_DIM + kbg * BK;
            uint32_t dst_row = stb + row * 256;
            int rx = row & 7;
#pragma unroll
            for (int i = 0; i < 4; i++) {
                int c = cg * 4 + i;
                cp_async16(dst_row + (uint32_t)((c ^ rx) * 16), src + c * 8);
            }
        }
        // W: qweight rows kbg*16..+16, channels nbase..+128 (512B/row, linear)
        {
            const uint32_t* wsrc = qweight + (size_t)(kbg * 16) * OUT_DIM + nbase;
            uint32_t dstW = stb + A_BYTES;
#pragma unroll
            for (int i = 0; i < 2; i++) {
                int id = t * 2 + i;          // 0..511
                int r = id >> 5, c = id & 31;
                cp_async16(dstW + (uint32_t)id * 16, wsrc + (size_t)r * OUT_DIM + c * 4);
            }
        }
        // S/Z: 128 floats each
        if (t < 32) {
            cp_async16(stb + S_OFF + t * 16, scales + (size_t)kbg * OUT_DIM + nbase + t * 4);
        } else if (t < 64) {
            int u = t - 32;
            cp_async16(stb + Z_OFF + u * 16, zeros + (size_t)kbg * OUT_DIM + nbase + u * 4);
        }
    };

    float acc[2][4][4];
#pragma unroll
    for (int nt = 0; nt < 2; nt++)
#pragma unroll
        for (int mt = 0; mt < 4; mt++)
#pragma unroll
            for (int i = 0; i < 4; i++) acc[nt][mt][i] = 0.f;

    const int lm_m  = lane & 15;    // row within m16 tile
    const int lm_kh = lane >> 4;    // k-half (0/1)
    const int lm_x  = lane & 7;     // row XOR key

    load_stage(0, kb0);
    CP_COMMIT();

#pragma unroll 1
    for (int kb = 0; kb < nkb; kb++) {
        const int s = kb & 1;
        CP_WAIT(0);          // only load(kb) outstanding -> wait for it
        __syncthreads();     // data visible to all warps; stage s^1 free
        if (kb + 1 < nkb) {
            load_stage(s ^ 1, kb0 + kb + 1);   // hidden behind this kb's compute
            CP_COMMIT();
        }

        const uint8_t*  stb  = sm + s * STAGE;
        const uint32_t  ab   = sbase + s * STAGE;
        const uint32_t* smW  = (const uint32_t*)(stb + A_BYTES);
        const float*    smS  = (const float*)(stb + S_OFF);
        const float*    smZ  = (const float*)(stb + Z_OFF);

        __half2 S2[2], B2[2];
#pragma unroll
        for (int nt = 0; nt < 2; nt++) {
            int nloc = wid * WARP_N + nt * 8 + nl;
            float sc = smS[nloc];
            float zr = smZ[nloc];
            S2[nt] = __float2half2_rn(sc);
            B2[nt] = __float2half2_rn(-zr * sc);
        }

#pragma unroll
        for (int s16 = 0; s16 < 8; s16++) {
            uint32_t a[4][4];
#pragma unroll
            for (int mt = 0; mt < 4; mt++) {
                int m = mt * 16 + lm_m;
                uint32_t addr = ab + (uint32_t)(m * 256)
                              + (uint32_t)(((2 * s16 + lm_kh) ^ lm_x) * 16);
                ldmatrix_x4(a[mt], addr);
            }
#pragma unroll
            for (int nt = 0; nt < 2; nt++) {
                int nloc = wid * WARP_N + nt * 8 + nl;
                uint32_t qlo = smW[(2 * s16)     * CTA_N + nloc];
                uint32_t qhi = smW[(2 * s16 + 1) * CTA_N + nloc];
                uint32_t b0 = dq_pair(qlo, 4 * kc, S2[nt], B2[nt]);
                uint32_t b1 = dq_pair(qhi, 4 * kc, S2[nt], B2[nt]);
#pragma unroll
                for (int mt = 0; mt < 4; mt++)
                    mma16816(acc[nt][mt], a[mt], b0, b1);
            }
        }
    }

    // ---- epilogue: accumulate into out via fire-and-forget global adds ----
#pragma unroll
    for (int nt = 0; nt < 2; nt++) {
        int n = nbase + wid * WARP_N + nt * 8 + (lane & 3) * 2;
#pragma unroll
        for (int mt = 0; mt < 4; mt++) {
            int m = mt * 16 + (lane >> 2);
            float* p0 = out + (size_t)m * OUT_DIM + n;
            float* p1 = out + (size_t)(m + 8) * OUT_DIM + n;
            redg_add(p0,     acc[nt][mt][0]);
            redg_add(p0 + 1, acc[nt][mt][1]);
            redg_add(p1,     acc[nt][mt][2]);
            redg_add(p1 + 1, acc[nt][mt][3]);
        }
    }
}

// ============================ launch ============================
extern "C" void kernel_launch(void* const* d_in, const int* in_sizes, int n_in,
                              void* d_out, int out_size) {
    (void)in_sizes; (void)n_in; (void)out_size;
    const float*    x       = (const float*)d_in[0];
    const uint32_t* qweight = (const uint32_t*)d_in[1];
    const float*    scales  = (const float*)d_in[2];
    const float*    zeros   = (const float*)d_in[3];
    // d_in[4] = g_idx (unused: g_idx[i] == i / GROUP by construction)
    float* out = (float*)d_out;

    xperm_kernel<<<(BATCH * IN_DIM / 8 + 255) / 256, 256>>>(x, out);

    cudaFuncSetAttribute(mpq_kernel, cudaFuncAttributeMaxDynamicSharedMemorySize, SMEM_ALLOC);
    mpq_kernel<<<NCTA, NTHREADS, SMEM_ALLOC>>>(qweight, scales, zeros, out);
}